// round 14
// baseline (speedup 1.0000x reference)
#include <cuda_runtime.h>
#include <cuda_fp16.h>
#include <stdint.h>
#include <math.h>

// Problem dims
#define T_      16384
#define D_      1024
#define E_      64
#define NE_     128
#define NNOISE  1048576

// Output layout (all float32, tuple order, flattened)
#define OUT_RW    0
#define OUT_IDX   32768
#define OUT_LOSS  65536
#define OUT_PROBS 65537
#define OUT_NSM   1114113

// Scratch (device globals)
__device__ float    g_sumprob[E_];
__device__ int      g_tok[E_];
__device__ float    g_nssum;
__device__ unsigned g_done;
__device__ __half   g_Wh[NE_ * D_];    // W fp16

// ---------------------------------------------------------------------------
// Threefry-2x32 (JAX-exact)
// ---------------------------------------------------------------------------
__host__ __device__ __forceinline__ uint32_t rotl32(uint32_t v, int d) {
    return (v << d) | (v >> (32 - d));
}

__host__ __device__ __forceinline__ void tf2x32(uint32_t k0, uint32_t k1,
                                                uint32_t x0, uint32_t x1,
                                                uint32_t& o0, uint32_t& o1) {
    uint32_t ks0 = k0, ks1 = k1, ks2 = 0x1BD11BDAu ^ k0 ^ k1;
    x0 += ks0; x1 += ks1;
    x0 += x1; x1 = rotl32(x1, 13); x1 ^= x0;
    x0 += x1; x1 = rotl32(x1, 15); x1 ^= x0;
    x0 += x1; x1 = rotl32(x1, 26); x1 ^= x0;
    x0 += x1; x1 = rotl32(x1,  6); x1 ^= x0;
    x0 += ks1; x1 += ks2 + 1u;
    x0 += x1; x1 = rotl32(x1, 17); x1 ^= x0;
    x0 += x1; x1 = rotl32(x1, 29); x1 ^= x0;
    x0 += x1; x1 = rotl32(x1, 16); x1 ^= x0;
    x0 += x1; x1 = rotl32(x1, 24); x1 ^= x0;
    x0 += ks2; x1 += ks0 + 2u;
    x0 += x1; x1 = rotl32(x1, 13); x1 ^= x0;
    x0 += x1; x1 = rotl32(x1, 15); x1 ^= x0;
    x0 += x1; x1 = rotl32(x1, 26); x1 ^= x0;
    x0 += x1; x1 = rotl32(x1,  6); x1 ^= x0;
    x0 += ks0; x1 += ks1 + 3u;
    x0 += x1; x1 = rotl32(x1, 17); x1 ^= x0;
    x0 += x1; x1 = rotl32(x1, 29); x1 ^= x0;
    x0 += x1; x1 = rotl32(x1, 16); x1 ^= x0;
    x0 += x1; x1 = rotl32(x1, 24); x1 ^= x0;
    x0 += ks1; x1 += ks2 + 4u;
    x0 += x1; x1 = rotl32(x1, 13); x1 ^= x0;
    x0 += x1; x1 = rotl32(x1, 15); x1 ^= x0;
    x0 += x1; x1 = rotl32(x1, 26); x1 ^= x0;
    x0 += x1; x1 = rotl32(x1,  6); x1 ^= x0;
    x0 += ks2; x1 += ks0 + 5u;
    o0 = x0; o1 = x1;
}

__device__ __forceinline__ float erfinv_xla(float x) {
    float w = -log1pf(-x * x);
    float p;
    if (w < 5.0f) {
        w -= 2.5f;
        p = 2.81022636e-08f;
        p = fmaf(p, w, 3.43273939e-07f);
        p = fmaf(p, w, -3.5233877e-06f);
        p = fmaf(p, w, -4.39150654e-06f);
        p = fmaf(p, w, 0.00021858087f);
        p = fmaf(p, w, -0.00125372503f);
        p = fmaf(p, w, -0.00417768164f);
        p = fmaf(p, w, 0.246640727f);
        p = fmaf(p, w, 1.50140941f);
    } else {
        w = sqrtf(w) - 3.0f;
        p = -0.000200214257f;
        p = fmaf(p, w, 0.000100950558f);
        p = fmaf(p, w, 0.00134934322f);
        p = fmaf(p, w, -0.00367342844f);
        p = fmaf(p, w, 0.00573950773f);
        p = fmaf(p, w, -0.0076224613f);
        p = fmaf(p, w, 0.00943887047f);
        p = fmaf(p, w, 1.00167406f);
        p = fmaf(p, w, 2.83297682f);
    }
    return p * x;
}

__device__ __forceinline__ float jax_normal(uint32_t k0, uint32_t k1, uint32_t i) {
    uint32_t b1, b2;
    tf2x32(k0, k1, 0u, i, b1, b2);
    uint32_t bits = b1 ^ b2;
    float f = __uint_as_float((bits >> 9) | 0x3F800000u) - 1.0f;
    const float lo = -0.99999994039535522461f;
    float u = fmaf(f, 2.0f, lo);
    u = fmaxf(u, lo);
    return 1.41421353816986083984f * erfinv_xla(u);
}

__device__ __forceinline__ float softplus_f(float x) {
    return fmaxf(x, 0.0f) + log1pf(__expf(-fabsf(x)));
}
__device__ __forceinline__ float softplus_exact(float x) {
    return fmaxf(x, 0.0f) + log1pf(expf(-fabsf(x)));
}

// sortable-float helpers
__device__ __forceinline__ uint32_t fsort(float z) {
    uint32_t b = __float_as_uint(z);
    return (b & 0x80000000u) ? ~b : (b | 0x80000000u);
}
__device__ __forceinline__ float funsort(uint32_t u) {
    uint32_t b = (u & 0x80000000u) ? (u ^ 0x80000000u) : ~u;
    return __uint_as_float(b);
}

// ---------------------------------------------------------------------------
// mma.sync helpers
// ---------------------------------------------------------------------------
__device__ __forceinline__ uint32_t smem_u32(const void* p) {
    uint32_t a;
    asm("{ .reg .u64 t; cvta.to.shared.u64 t, %1; cvt.u32.u64 %0, t; }" : "=r"(a) : "l"(p));
    return a;
}

__device__ __forceinline__ void ldsm_x4(uint32_t* r, uint32_t addr) {
    asm volatile("ldmatrix.sync.aligned.m8n8.x4.shared.b16 {%0,%1,%2,%3}, [%4];"
                 : "=r"(r[0]), "=r"(r[1]), "=r"(r[2]), "=r"(r[3]) : "r"(addr));
}

__device__ __forceinline__ void mma16816(float* d, const uint32_t* a, const uint32_t* b) {
    asm volatile(
        "mma.sync.aligned.m16n8k16.row.col.f32.f16.f16.f32 "
        "{%0,%1,%2,%3}, {%4,%5,%6,%7}, {%8,%9}, {%0,%1,%2,%3};"
        : "+f"(d[0]), "+f"(d[1]), "+f"(d[2]), "+f"(d[3])
        : "r"(a[0]), "r"(a[1]), "r"(a[2]), "r"(a[3]), "r"(b[0]), "r"(b[1]));
}

__device__ __forceinline__ void cpasync16(uint32_t dst, const void* src) {
    asm volatile("cp.async.cg.shared.global [%0], [%1], 16;" :: "r"(dst), "l"(src) : "memory");
}

// ---------------------------------------------------------------------------
// prep: W -> fp16 + zero accumulators
// ---------------------------------------------------------------------------
__global__ void prep_w_kernel(const float* __restrict__ Wg, const float* __restrict__ Wn) {
    int idx = blockIdx.x * 256 + threadIdx.x;
    int r = idx >> 10, k = idx & 1023;
    float v = (r < E_) ? Wg[r * D_ + k] : Wn[(r - E_) * D_ + k];
    g_Wh[idx] = __float2half_rn(v);
    if (blockIdx.x == 0) {
        int i = threadIdx.x;
        if (i < E_) { g_sumprob[i] = 0.0f; g_tok[i] = 0; }
        if (i == E_) g_nssum = 0.0f;
        if (i == E_ + 1) g_done = 0u;
    }
}

// ---------------------------------------------------------------------------
// Fused GEMM (BM=64, fp16, triple-buffered W) + interleaved noise + router
// ---------------------------------------------------------------------------
#define BM      64
#define BK      64
#define STR     72
#define XSPLIT  (BM * STR * 2)         // 9216 B
#define WSPLIT  (NE_ * STR * 2)        // 18432 B
#define XBASE   0
#define WBASE   (2 * XSPLIT)           // 18432
#define NVBUF   (WBASE + 3 * WSPLIT)   // 73728
#define SMEM_TOT (NVBUF + 16384)       // 90112 B
#define LSTR    132
#define MARGIN  2.5e-2f

__device__ __forceinline__ float coop_dot(const float4* xv, const float* __restrict__ W,
                                          int lane) {
    float s = 0.f;
#pragma unroll
    for (int j = 0; j < 8; j++) {
        float4 w = *(const float4*)(W + lane * 4 + j * 128);
        s = fmaf(xv[j].x, w.x, s);
        s = fmaf(xv[j].y, w.y, s);
        s = fmaf(xv[j].z, w.z, s);
        s = fmaf(xv[j].w, w.w, s);
    }
#pragma unroll
    for (int off = 16; off; off >>= 1) s += __shfl_xor_sync(0xFFFFFFFFu, s, off);
    return s;
}

__global__ __launch_bounds__(256, 2) void fused_kernel(float* __restrict__ out,
                                                       const float* __restrict__ X,
                                                       const float* __restrict__ Wg,
                                                       const float* __restrict__ Wn,
                                                       uint32_t k0, uint32_t k1) {
    extern __shared__ char smem[];
    __shared__ float s_prob[E_];
    __shared__ int   s_tok[E_];
    __shared__ float s_ns;
    __shared__ int   s_last;

    const uint32_t sb = smem_u32(smem);
    const int tid = threadIdx.x;
    const int lane = tid & 31, wid = tid >> 5;
    const int m0 = blockIdx.x * BM;
    const unsigned FULL = 0xFFFFFFFFu;
    float* nvb = (float*)(smem + NVBUF);   // [64 tokens][64 lanes]

    if (tid < E_) { s_prob[tid] = 0.0f; s_tok[tid] = 0; }
    if (tid == 0) { s_ns = 0.0f; s_last = 0; }

    // ================= GEMM phase =================
    float4 xr[4];

    auto load_x = [&](int kt) {
#pragma unroll
        for (int it = 0; it < 4; it++) {
            int idx = tid + it * 256;
            int r = idx >> 4, c4 = (idx & 15) << 2;
            xr[it] = *(const float4*)(X + (size_t)(m0 + r) * D_ + kt * BK + c4);
        }
    };
    auto store_x = [&](int buf) {
        uint32_t base = sb + XBASE + buf * XSPLIT;
#pragma unroll
        for (int it = 0; it < 4; it++) {
            int idx = tid + it * 256;
            int r = idx >> 4, c4 = (idx & 15) << 2;
            uint32_t off = (uint32_t)(r * STR + c4) * 2;
            __half2 h0 = __floats2half2_rn(xr[it].x, xr[it].y);
            __half2 h1 = __floats2half2_rn(xr[it].z, xr[it].w);
            asm volatile("st.shared.v2.b32 [%0], {%1,%2};"
                         :: "r"(base + off), "r"(*(uint32_t*)&h0), "r"(*(uint32_t*)&h1) : "memory");
        }
    };
    auto load_w = [&](int kt, int wbuf) {
        uint32_t bbase = sb + WBASE + wbuf * WSPLIT;
#pragma unroll
        for (int it = 0; it < 4; it++) {
            int idx = tid + it * 256;
            int r = idx >> 3, c8 = (idx & 7) << 3;
            uint32_t off = (uint32_t)(r * STR + c8) * 2;
            cpasync16(bbase + off, g_Wh + (size_t)r * D_ + kt * BK + c8);
        }
        asm volatile("cp.async.commit_group;" ::: "memory");
    };

    const int wm = wid & 1, wn = wid >> 1;   // warp tile: 32 rows x 32 cols
    float acc[2][4][4];
#pragma unroll
    for (int a = 0; a < 2; a++)
#pragma unroll
        for (int b = 0; b < 4; b++)
#pragma unroll
            for (int c = 0; c < 4; c++) acc[a][b][c] = 0.0f;

    // prologue: W(0), W(1) in flight; X(0) staged
    load_w(0, 0);
    load_w(1, 1);
    load_x(0);
    store_x(0);
    asm volatile("cp.async.wait_group 1;" ::: "memory");   // W(0) done
    __syncthreads();

    int wb = 0;                     // wbuf index of current kt
    for (int kt = 0; kt < 16; kt++) {
        if (kt + 2 < 16) {
            int nb = wb + 2; if (nb >= 3) nb -= 3;
            load_w(kt + 2, nb);
        }
        if (kt + 1 < 16) load_x(kt + 1);

        const uint32_t Ab = sb + XBASE + (kt & 1) * XSPLIT;
        const uint32_t Bb = sb + WBASE + wb * WSPLIT;
#pragma unroll
        for (int s = 0; s < 4; s++) {
            const int kk0 = s * 16;
            uint32_t ah[2][4], bh[4][2];
            const int aRow = wm * 32 + (lane & 15);
            const int aCol = kk0 + ((lane >> 4) << 3);
#pragma unroll
            for (int mt = 0; mt < 2; mt++) {
                uint32_t ad = Ab + (uint32_t)((aRow + mt * 16) * STR + aCol) * 2;
                ldsm_x4(ah[mt], ad);
            }
            {
                const int g = lane >> 3;
                const int sub = g >> 1, kh = g & 1;
#pragma unroll
                for (int p = 0; p < 2; p++) {
                    uint32_t bd = Bb + (uint32_t)((wn * 32 + (p * 2 + sub) * 8 + (lane & 7)) * STR
                                                  + kk0 + kh * 8) * 2;
                    ldsm_x4(&bh[p * 2][0], bd);
                }
            }
#pragma unroll
            for (int mt = 0; mt < 2; mt++)
#pragma unroll
                for (int nt = 0; nt < 4; nt++)
                    mma16816(acc[mt][nt], ah[mt], bh[nt]);
        }

        // interleaved noise generation: 1 token per warp every 2 iterations
        if ((kt & 1) == 0) {
            const int tok = wid * 8 + (kt >> 1);
            const uint32_t tbase = (uint32_t)(m0 + tok) * 64;
            float a = jax_normal(k0, k1, tbase + lane);
            float b = jax_normal(k0, k1, tbase + 32 + lane);
            nvb[tok * 64 + lane]      = a;
            nvb[tok * 64 + 32 + lane] = b;
        }

        if (kt + 1 < 16) {
            store_x((kt + 1) & 1);
            if (kt + 2 < 16) {
                asm volatile("cp.async.wait_group 1;" ::: "memory");  // W(kt+1) done
            } else {
                asm volatile("cp.async.wait_group 0;" ::: "memory");
            }
        }
        __syncthreads();

        wb++; if (wb >= 3) wb -= 3;
    }

    // write logits to smem (64*132*4 = 33792 fits in X+W region)
    float* sL = (float*)smem;
    {
        const int row = wm * 32 + (lane >> 2);
        const int col = wn * 32 + ((lane & 3) << 1);
#pragma unroll
        for (int mt = 0; mt < 2; mt++)
#pragma unroll
            for (int nt = 0; nt < 4; nt++) {
                *(float2*)(sL + (row + mt * 16) * LSTR + col + nt * 8) =
                    make_float2(acc[mt][nt][0], acc[mt][nt][1]);
                *(float2*)(sL + (row + mt * 16 + 8) * LSTR + col + nt * 8) =
                    make_float2(acc[mt][nt][2], acc[mt][nt][3]);
            }
    }
    __syncthreads();

    // ================= Router phase: 8 tokens/warp, 2 at a time =============
    const int e0 = lane, e1 = lane + 32;
    float p0_acc = 0.f, p1_acc = 0.f, ns_acc = 0.f;

    for (int ii = 0; ii < 4; ii++) {
        const int wt = wid * 8 + ii * 2;

        float c0[2], c1[2], n0[2], n1[2];
#pragma unroll
        for (int j = 0; j < 2; j++) {
            const float* rp = sL + (wt + j) * LSTR;
            c0[j] = rp[lane];      c1[j] = rp[32 + lane];
            n0[j] = rp[64 + lane]; n1[j] = rp[96 + lane];
        }

        float sp0[2], sp1[2], nv0[2], nv1[2], z0[2], z1[2];
#pragma unroll
        for (int j = 0; j < 2; j++) {
            sp0[j] = softplus_f(n0[j]);
            sp1[j] = softplus_f(n1[j]);
            nv0[j] = nvb[(wt + j) * 64 + lane];
            nv1[j] = nvb[(wt + j) * 64 + 32 + lane];
            z0[j] = c0[j] + nv0[j] * sp0[j];
            z1[j] = c1[j] + nv1[j] * sp1[j];
        }

        // merged top-2 butterfly (both tokens interleaved)
        uint64_t hi[2], lo[2];
#pragma unroll
        for (int j = 0; j < 2; j++) {
            uint64_t key0 = ((uint64_t)fsort(z0[j]) << 32) | (uint32_t)(63 - e0);
            uint64_t key1 = ((uint64_t)fsort(z1[j]) << 32) | (uint32_t)(63 - e1);
            hi[j] = key0 > key1 ? key0 : key1;
            lo[j] = key0 > key1 ? key1 : key0;
        }
#pragma unroll
        for (int off = 16; off; off >>= 1) {
#pragma unroll
            for (int j = 0; j < 2; j++) {
                uint64_t oh = __shfl_xor_sync(FULL, hi[j], off);
                uint64_t ol = __shfl_xor_sync(FULL, lo[j], off);
                uint64_t mx = hi[j] > oh ? hi[j] : oh;
                uint64_t mn = hi[j] > oh ? oh : hi[j];
                uint64_t l2 = lo[j] > ol ? lo[j] : ol;
                hi[j] = mx;
                lo[j] = mn > l2 ? mn : l2;
            }
        }

        // clean softmax sums (interleaved chains)
        float q0[2], q1[2], sc[2];
#pragma unroll
        for (int j = 0; j < 2; j++) {
            q0[j] = __expf(c0[j]); q1[j] = __expf(c1[j]);
            sc[j] = q0[j] + q1[j];
        }
#pragma unroll
        for (int off = 16; off; off >>= 1) {
#pragma unroll
            for (int j = 0; j < 2; j++)
                sc[j] += __shfl_xor_sync(FULL, sc[j], off);
        }

#pragma unroll
        for (int j = 0; j < 2; j++) {
            const int t = m0 + wt + j;
            float m1v = funsort((uint32_t)(hi[j] >> 32));
            int   m1i = 63 - (int)(hi[j] & 0xFFFFFFFFu);
            float m2v = funsort((uint32_t)(lo[j] >> 32));
            int   m2i = 63 - (int)(lo[j] & 0xFFFFFFFFu);

            const float thr = m2v - MARGIN;
            unsigned mask0 = __ballot_sync(FULL, z0[j] >= thr);
            unsigned mask1 = __ballot_sync(FULL, z1[j] >= thr);
            int cnt = __popc(mask0) + __popc(mask1);

            if ((m1v - m2v < MARGIN) || (cnt > 2)) {
                const float* xrow = X + (size_t)t * D_;
                float4 xv[8];
#pragma unroll
                for (int q = 0; q < 8; q++) xv[q] = *(const float4*)(xrow + lane * 4 + q * 128);

                float b1v = -INFINITY, b2v = -INFINITY;
                int   b1i = 0, b2i = 0;
                while (mask0 | mask1) {
                    int l0 = mask0 ? __ffs(mask0) - 1 : 64;
                    int l1 = mask1 ? __ffs(mask1) - 1 : 64;
                    int e; float nv;
                    if (l0 <= l1) { e = l0;      nv = __shfl_sync(FULL, nv0[j], l0); mask0 &= mask0 - 1; }
                    else          { e = l1 + 32; nv = __shfl_sync(FULL, nv1[j], l1); mask1 &= mask1 - 1; }
                    float ce = coop_dot(xv, Wg + (size_t)e * D_, lane);
                    float ne = coop_dot(xv, Wn + (size_t)e * D_, lane);
                    float ze = ce + nv * softplus_exact(ne);
                    if (ze > b1v) { b2v = b1v; b2i = b1i; b1v = ze; b1i = e; }
                    else if (ze > b2v) { b2v = ze; b2i = e; }
                }
                m1v = b1v; m1i = b1i;
                m2v = b2v; m2i = b2i;
            }

            const float e21 = __expf(m2v - m1v);
            const float winv = 1.0f / (1.0f + e21);

            float inv = 1.0f / sc[j];
            float qq0 = q0[j] * inv, qq1 = q1[j] * inv;

            out[OUT_PROBS + (size_t)t * E_ + lane]      = qq0;
            out[OUT_PROBS + (size_t)t * E_ + 32 + lane] = qq1;
            p0_acc += qq0; p1_acc += qq1;
            ns_acc += sp0[j] + sp1[j];

            if (lane == 0) {
                out[OUT_RW  + t * 2 + 0] = winv;
                out[OUT_RW  + t * 2 + 1] = e21 * winv;
                out[OUT_IDX + t * 2 + 0] = (float)m1i;
                out[OUT_IDX + t * 2 + 1] = (float)m2i;
                atomicAdd(&s_tok[m1i], 1);
                atomicAdd(&s_tok[m2i], 1);
            }
        }
    }

    atomicAdd(&s_prob[e0], p0_acc);
    atomicAdd(&s_prob[e1], p1_acc);
#pragma unroll
    for (int off = 16; off; off >>= 1) ns_acc += __shfl_xor_sync(FULL, ns_acc, off);
    if (lane == 0) atomicAdd(&s_ns, ns_acc);
    __syncthreads();

    if (tid < E_) {
        atomicAdd(&g_sumprob[tid], s_prob[tid]);
        atomicAdd(&g_tok[tid], s_tok[tid]);
    }
    if (tid == 0) atomicAdd(&g_nssum, s_ns);

    // ================= last-CTA finalize =================
    __threadfence();
    if (tid == 0) {
        unsigned old = atomicAdd(&g_done, 1u);
        s_last = (old == gridDim.x - 1);
    }
    __syncthreads();
    if (s_last) {
        if (tid < E_) {
            float sp = atomicAdd(&g_sumprob[tid], 0.0f);
            int   tk = atomicAdd(&g_tok[tid], 0);
            s_prob[tid] = ((float)tk / (float)T_) * (sp / (float)T_);
        }
        __syncthreads();
        if (tid == 0) {
            float acc2 = 0.0f;
            for (int i = 0; i < E_; i++) acc2 += s_prob[i];
            out[OUT_LOSS] = 0.64f * acc2;
            out[OUT_NSM]  = atomicAdd(&g_nssum, 0.0f) / (float)NNOISE;
        }
    }
}

// ---------------------------------------------------------------------------
extern "C" void kernel_launch(void* const* d_in, const int* in_sizes, int n_in,
                              void* d_out, int out_size) {
    const float* x  = (const float*)d_in[0];
    const float* Wg = (const float*)d_in[1];
    const float* Wn = (const float*)d_in[2];
    float* out = (float*)d_out;

    uint32_t nk0, nk1;
    tf2x32(0u, 0u, 0u, 12345u, nk0, nk1);

    static bool attr_set = false;
    if (!attr_set) {
        cudaFuncSetAttribute(fused_kernel, cudaFuncAttributeMaxDynamicSharedMemorySize, SMEM_TOT);
        attr_set = true;
    }

    prep_w_kernel<<<512, 256>>>(Wg, Wn);
    fused_kernel<<<T_ / BM, 256, SMEM_TOT>>>(out, x, Wg, Wn, nk0, nk1);
}